// round 1
// baseline (speedup 1.0000x reference)
#include <cuda_runtime.h>
#include <math.h>

#define NTHREADS 256
#define OPT 8                       // outputs per thread
#define TILE (NTHREADS * OPT)       // 2048 samples per block
#define NTAPS 5
#define NSAMP 131072
#define BATCH 64
#define FS_F 30720000.0f
#define SCS_F 15000.0f
#define MAX_CFO_F 0.05f
#define TWO_PI_F 6.28318530717958647692f

__global__ __launch_bounds__(NTHREADS)
void wireless_channel_kernel(
    const float* __restrict__ x_real,  const float* __restrict__ x_imag,
    const float* __restrict__ ebno_db, const float* __restrict__ cfo_u,
    const float* __restrict__ taps_real, const float* __restrict__ taps_imag,
    const float* __restrict__ noise_real, const float* __restrict__ noise_imag,
    float* __restrict__ out)
{
    const int b    = blockIdx.y;
    const int n0   = blockIdx.x * TILE + threadIdx.x * OPT;  // first output sample

    // ---- per-row scalars (broadcast loads) ----
    const float cfo    = cfo_u[b];
    const float deltaf = (cfo * 2.0f - 1.0f) * MAX_CFO_F * SCS_F;
    const float w      = (TWO_PI_F * deltaf) / FS_F;          // rad / sample
    // snr_db = ebno + 10*log10(1.5); scale = 0.5 * 10^(-snr/20)
    const float snr    = ebno_db[b] + 1.7609125905568124f;
    const float scale  = 0.5f * exp2f(-snr * 0.16609640474436813f); // log2(10)/20

    float tr[NTAPS], ti[NTAPS];
    #pragma unroll
    for (int k = 0; k < NTAPS; k++) {
        tr[k] = taps_real[b * NTAPS + k];
        ti[k] = taps_imag[b * NTAPS + k];
    }

    const float* __restrict__ xr_row = x_real + (size_t)b * NSAMP;
    const float* __restrict__ xi_row = x_imag + (size_t)b * NSAMP;

    // ---- rotated window [n0-2, n0+OPT+1] in registers (halo 2 each side) ----
    float rxr[OPT + 4], rxi[OPT + 4];
    float s, c, sw, cw;
    __sincosf(w * (float)(n0 - 2), &s, &c);   // phase at first halo sample
    __sincosf(w, &sw, &cw);                   // per-sample rotation step

    #pragma unroll
    for (int i = 0; i < OPT + 4; i++) {
        const int g = n0 - 2 + i;
        float xr = 0.0f, xi = 0.0f;
        if (g >= 0 && g < NSAMP) { xr = xr_row[g]; xi = xi_row[g]; }
        rxr[i] = xr * c - xi * s;
        rxi[i] = xr * s + xi * c;
        const float c2 = c * cw - s * sw;     // advance phase by w
        const float s2 = c * sw + s * cw;
        c = c2; s = s2;
    }

    // ---- noise (vectorized, n0 is 32B-aligned) ----
    const float4* __restrict__ nr4 = (const float4*)(noise_real + (size_t)b * NSAMP + n0);
    const float4* __restrict__ ni4 = (const float4*)(noise_imag + (size_t)b * NSAMP + n0);
    float4 nr[2] = { nr4[0], nr4[1] };
    float4 ni[2] = { ni4[0], ni4[1] };
    const float* nrp = (const float*)nr;
    const float* nip = (const float*)ni;

    // ---- 5-tap complex conv + AWGN ----
    float yr[OPT], yi[OPT];
    #pragma unroll
    for (int j = 0; j < OPT; j++) {
        float s_rr = 0.0f, s_ii = 0.0f, s_ri = 0.0f, s_ir = 0.0f;
        #pragma unroll
        for (int k = 0; k < NTAPS; k++) {
            s_rr = fmaf(tr[k], rxr[j + k], s_rr);
            s_ii = fmaf(ti[k], rxi[j + k], s_ii);
            s_ir = fmaf(ti[k], rxr[j + k], s_ir);
            s_ri = fmaf(tr[k], rxi[j + k], s_ri);
        }
        yr[j] = (s_rr - s_ii) + nrp[j] * scale;
        yi[j] = (s_ir + s_ri) + nip[j] * scale;
    }

    // ---- vectorized stores: out[0,b,:] = real, out[1,b,:] = imag ----
    float4* outr = (float4*)(out + (size_t)b * NSAMP + n0);
    float4* outi = (float4*)(out + (size_t)BATCH * NSAMP + (size_t)b * NSAMP + n0);
    outr[0] = make_float4(yr[0], yr[1], yr[2], yr[3]);
    outr[1] = make_float4(yr[4], yr[5], yr[6], yr[7]);
    outi[0] = make_float4(yi[0], yi[1], yi[2], yi[3]);
    outi[1] = make_float4(yi[4], yi[5], yi[6], yi[7]);
}

extern "C" void kernel_launch(void* const* d_in, const int* in_sizes, int n_in,
                              void* d_out, int out_size)
{
    const float* x_real     = (const float*)d_in[0];
    const float* x_imag     = (const float*)d_in[1];
    const float* ebno_db    = (const float*)d_in[2];
    const float* cfo_u      = (const float*)d_in[3];
    const float* taps_real  = (const float*)d_in[4];
    const float* taps_imag  = (const float*)d_in[5];
    const float* noise_real = (const float*)d_in[6];
    const float* noise_imag = (const float*)d_in[7];
    float* out = (float*)d_out;

    dim3 grid(NSAMP / TILE, BATCH);   // (64, 64)
    wireless_channel_kernel<<<grid, NTHREADS>>>(
        x_real, x_imag, ebno_db, cfo_u, taps_real, taps_imag,
        noise_real, noise_imag, out);
}

// round 2
// speedup vs baseline: 1.1963x; 1.1963x over previous
#include <cuda_runtime.h>
#include <math.h>

#define NTHREADS 256
#define OPT 8                       // outputs per thread
#define TILE (NTHREADS * OPT)       // 2048 samples per block
#define NTAPS 5
#define NSAMP 131072
#define BATCH 64
#define FS_F 30720000.0f
#define SCS_F 15000.0f
#define MAX_CFO_F 0.05f
#define TWO_PI_F 6.28318530717958647692f

__global__ __launch_bounds__(NTHREADS)
void wireless_channel_kernel(
    const float* __restrict__ x_real,  const float* __restrict__ x_imag,
    const float* __restrict__ ebno_db, const float* __restrict__ cfo_u,
    const float* __restrict__ taps_real, const float* __restrict__ taps_imag,
    const float* __restrict__ noise_real, const float* __restrict__ noise_imag,
    float* __restrict__ out)
{
    const int b    = blockIdx.y;
    const int n0   = blockIdx.x * TILE + threadIdx.x * OPT;  // first output sample

    // ---- per-row scalars (broadcast loads) ----
    const float cfo    = cfo_u[b];
    const float deltaf = (cfo * 2.0f - 1.0f) * MAX_CFO_F * SCS_F;
    const float w      = (TWO_PI_F * deltaf) / FS_F;          // rad / sample
    // snr_db = ebno + 10*log10(1.5); scale = 0.5 * 10^(-snr/20)
    const float snr    = ebno_db[b] + 1.7609125905568124f;
    const float scale  = 0.5f * exp2f(-snr * 0.16609640474436813f); // log2(10)/20

    float tr[NTAPS], ti[NTAPS];
    #pragma unroll
    for (int k = 0; k < NTAPS; k++) {
        tr[k] = taps_real[b * NTAPS + k];
        ti[k] = taps_imag[b * NTAPS + k];
    }

    const float* __restrict__ xr_row = x_real + (size_t)b * NSAMP;
    const float* __restrict__ xi_row = x_imag + (size_t)b * NSAMP;

    // ---- fetch raw window: need samples [n0-2, n0+9]; fast path loads the
    //      16B-aligned superset [n0-4, n0+12) as 4x float4 per array.
    float xrb[16], xib[16];
    if (n0 >= 4 && n0 + 12 <= NSAMP) {
        const float4* __restrict__ xr4 = (const float4*)(xr_row + n0 - 4);
        const float4* __restrict__ xi4 = (const float4*)(xi_row + n0 - 4);
        #pragma unroll
        for (int v = 0; v < 4; v++) {
            ((float4*)xrb)[v] = xr4[v];
            ((float4*)xib)[v] = xi4[v];
        }
    } else {
        // row-edge lanes: scalar loads with zero padding (2 lanes per row)
        #pragma unroll
        for (int i = 0; i < 16; i++) {
            const int g = n0 - 4 + i;
            float xr = 0.0f, xi = 0.0f;
            if (g >= 0 && g < NSAMP) { xr = xr_row[g]; xi = xi_row[g]; }
            xrb[i] = xr; xib[i] = xi;
        }
    }

    // ---- CFO rotation of window [n0-2, n0+9] via phase recurrence ----
    float rxr[OPT + 4], rxi[OPT + 4];
    float s, c, sw, cw;
    __sincosf(w * (float)(n0 - 2), &s, &c);   // phase at first halo sample
    __sincosf(w, &sw, &cw);                   // per-sample rotation step

    #pragma unroll
    for (int i = 0; i < OPT + 4; i++) {
        const float xr = xrb[i + 2];
        const float xi = xib[i + 2];
        rxr[i] = xr * c - xi * s;
        rxi[i] = xr * s + xi * c;
        const float c2 = c * cw - s * sw;     // advance phase by w
        const float s2 = c * sw + s * cw;
        c = c2; s = s2;
    }

    // ---- noise (vectorized, n0 is 32B-aligned) ----
    const float4* __restrict__ nr4 = (const float4*)(noise_real + (size_t)b * NSAMP + n0);
    const float4* __restrict__ ni4 = (const float4*)(noise_imag + (size_t)b * NSAMP + n0);
    float4 nr[2] = { nr4[0], nr4[1] };
    float4 ni[2] = { ni4[0], ni4[1] };
    const float* nrp = (const float*)nr;
    const float* nip = (const float*)ni;

    // ---- 5-tap complex conv + AWGN ----
    float yr[OPT], yi[OPT];
    #pragma unroll
    for (int j = 0; j < OPT; j++) {
        float s_rr = 0.0f, s_ii = 0.0f, s_ri = 0.0f, s_ir = 0.0f;
        #pragma unroll
        for (int k = 0; k < NTAPS; k++) {
            s_rr = fmaf(tr[k], rxr[j + k], s_rr);
            s_ii = fmaf(ti[k], rxi[j + k], s_ii);
            s_ir = fmaf(ti[k], rxr[j + k], s_ir);
            s_ri = fmaf(tr[k], rxi[j + k], s_ri);
        }
        yr[j] = (s_rr - s_ii) + nrp[j] * scale;
        yi[j] = (s_ir + s_ri) + nip[j] * scale;
    }

    // ---- vectorized stores: out[0,b,:] = real, out[1,b,:] = imag ----
    float4* outr = (float4*)(out + (size_t)b * NSAMP + n0);
    float4* outi = (float4*)(out + (size_t)BATCH * NSAMP + (size_t)b * NSAMP + n0);
    outr[0] = make_float4(yr[0], yr[1], yr[2], yr[3]);
    outr[1] = make_float4(yr[4], yr[5], yr[6], yr[7]);
    outi[0] = make_float4(yi[0], yi[1], yi[2], yi[3]);
    outi[1] = make_float4(yi[4], yi[5], yi[6], yi[7]);
}

extern "C" void kernel_launch(void* const* d_in, const int* in_sizes, int n_in,
                              void* d_out, int out_size)
{
    const float* x_real     = (const float*)d_in[0];
    const float* x_imag     = (const float*)d_in[1];
    const float* ebno_db    = (const float*)d_in[2];
    const float* cfo_u      = (const float*)d_in[3];
    const float* taps_real  = (const float*)d_in[4];
    const float* taps_imag  = (const float*)d_in[5];
    const float* noise_real = (const float*)d_in[6];
    const float* noise_imag = (const float*)d_in[7];
    float* out = (float*)d_out;

    dim3 grid(NSAMP / TILE, BATCH);   // (64, 64)
    wireless_channel_kernel<<<grid, NTHREADS>>>(
        x_real, x_imag, ebno_db, cfo_u, taps_real, taps_imag,
        noise_real, noise_imag, out);
}